// round 9
// baseline (speedup 1.0000x reference)
#include <cuda_runtime.h>

// SORF fused: out[m] = (1/64) * sum_a alpha . cos( (1/16) H (D_s ⊙ (rep[m,a] @ red[s])) + bias_s )
// Phase 1: GEMV f32x2, reductors read once/CTA, rh-partials tree-merged in smem (no atomics).
// Phase 2: warp = (atom, j-half); two stacks (j, j+8) processed per iteration with f32x2-packed
//          butterflies (x is stack-invariant -> dup-packed); bias/alpha pair-interleaved.

#define ATOMS 8
#define NATOMS 2048
#define MAXCHUNK 260

typedef unsigned long long ull;

__device__ int g_count[4];
__device__ int g_list[4 * NATOMS];
__device__ int g_tabS[MAXCHUNK];
__device__ int g_tabStart[MAXCHUNK];
__device__ int g_nchunks;
__device__ ull g_apack[4096];   // alpha pair-interleaved: [pi][p], pi -> (jb, jb+8)

__device__ __forceinline__ ull pack2(float a, float b) {
    ull r; asm("mov.b64 %0, {%1, %2};" : "=l"(r) : "f"(a), "f"(b)); return r;
}
__device__ __forceinline__ float2 unpack2(ull v) {
    float2 r; asm("mov.b64 {%0, %1}, %2;" : "=f"(r.x), "=f"(r.y) : "l"(v)); return r;
}
__device__ __forceinline__ void ffma2(ull& acc, ull a, ull b) {
    asm("fma.rn.f32x2 %0, %1, %2, %0;" : "+l"(acc) : "l"(a), "l"(b));
}
__device__ __forceinline__ ull add2(ull a, ull b) {
    ull r; asm("add.rn.f32x2 %0, %1, %2;" : "=l"(r) : "l"(a), "l"(b)); return r;
}
__device__ __forceinline__ ull sub2(ull a, ull b) {
    ull r; asm("sub.rn.f32x2 %0, %1, %2;" : "=l"(r) : "l"(a), "l"(b)); return r;
}
__device__ __forceinline__ ull sgn2(ull x, unsigned mlo, unsigned mhi) {
    ull r;
    asm("{\n\t.reg .b32 lo, hi;\n\tmov.b64 {lo, hi}, %1;\n\t"
        "xor.b32 lo, lo, %2;\n\txor.b32 hi, hi, %3;\n\tmov.b64 %0, {lo, hi};\n\t}"
        : "=l"(r) : "l"(x), "r"(mlo), "r"(mhi));
    return r;
}
__device__ __forceinline__ ull shfl2(ull x, int m) {
    float2 v = unpack2(x);
    v.x = __shfl_xor_sync(0xffffffffu, v.x, m);
    v.y = __shfl_xor_sync(0xffffffffu, v.y, m);
    return pack2(v.x, v.y);
}
#define BFLY2(a, b) do { ull t_ = (a); (a) = add2(t_, (b)); (b) = sub2(t_, (b)); } while (0)

// ---- prep: charges compaction, chunk table, packed-alpha table ----
__global__ void prep_kernel(const int* __restrict__ charges,
                            const float* __restrict__ alpha,
                            float* __restrict__ out) {
    __shared__ int chS[NATOMS];
    __shared__ int cntS[4];
    const int tid = threadIdx.x;          // 256 threads
    if (tid < 32) out[tid] = 0.0f;
    #pragma unroll
    for (int i = 0; i < NATOMS / 256; ++i) chS[tid + 256 * i] = charges[tid + 256 * i];
    // packed alpha: pi in 0..15 -> stacks (jb, jb+8), jb = pi<8 ? pi : pi+8
    for (int g = tid; g < 1024; g += 256) {
        int pi = g >> 6, p4 = g & 63;
        int jb = (pi < 8) ? pi : pi + 8;
        float4 lo = __ldg((const float4*)alpha + jb * 64 + p4);
        float4 hi = __ldg((const float4*)alpha + (jb + 8) * 64 + p4);
        ull* dst = g_apack + pi * 256 + p4 * 4;
        dst[0] = pack2(lo.x, hi.x); dst[1] = pack2(lo.y, hi.y);
        dst[2] = pack2(lo.z, hi.z); dst[3] = pack2(lo.w, hi.w);
    }
    __syncthreads();
    const int lane = tid & 31;
    const int w = tid >> 5;
    if (w < 4) {
        int cnt = 0;
        const unsigned lt = (1u << lane) - 1u;
        #pragma unroll 1
        for (int base = 0; base < NATOMS; base += 32) {
            int c = chS[base + lane];
            unsigned m = __ballot_sync(0xffffffffu, c == w);
            if (c == w) g_list[w * NATOMS + cnt + __popc(m & lt)] = base + lane;
            cnt += __popc(m);
        }
        if (lane == 0) { g_count[w] = cnt; cntS[w] = cnt; }
    }
    __syncthreads();
    int offs[5];
    offs[0] = 0;
    #pragma unroll
    for (int s = 0; s < 4; ++s) offs[s + 1] = offs[s] + ((cntS[s] + ATOMS - 1) / ATOMS);
    for (int c = tid; c < offs[4]; c += 256) {
        int s = (c >= offs[1]) + (c >= offs[2]) + (c >= offs[3]);
        g_tabS[c] = s;
        g_tabStart[c] = (c - offs[s]) * ATOMS;
    }
    if (tid == 0) g_nchunks = offs[4];
}

__global__ void __launch_bounds__(512, 2) sorf_kernel(
    const float* __restrict__ rep,
    const float* __restrict__ reductors,
    const float* __restrict__ Dmat,
    const float* __restrict__ bias,
    float* __restrict__ out)
{
    const int c = blockIdx.x;
    if (c >= g_nchunks) return;
    const int s = g_tabS[c];
    const int start = g_tabStart[c];
    const int n = g_count[s];
    const int cnt = min(ATOMS, n - start);

    // 32 KB multi-use: phase1 rep {v,v} pairs -> merge scratch (4 x 8KB slices) -> packed bias
    __shared__ ull bufS[ATOMS * 512];
    __shared__ unsigned dbitsS[256];
    __shared__ int atomsS[ATOMS];
    __shared__ float wpartS[16];

    const int tid = threadIdx.x;
    const int lane = tid & 31;
    const int w = tid >> 5;

    if (tid < ATOMS) atomsS[tid] = (tid < cnt) ? g_list[s * NATOMS + start + tid] : -1;
    __syncthreads();

    // rep -> duplicated pairs
    #pragma unroll
    for (int it = 0; it < 2; ++it) {
        int idx = tid + 512 * it;
        int ai = idx >> 7, q = idx & 127;
        int atom = atomsS[ai];
        float4 v = (atom >= 0) ? ((const float4*)rep)[(size_t)atom * 128 + q]
                               : make_float4(0.f, 0.f, 0.f, 0.f);
        ull* d = bufS + ai * 512 + q * 4;
        d[0] = pack2(v.x, v.x); d[1] = pack2(v.y, v.y);
        d[2] = pack2(v.z, v.z); d[3] = pack2(v.w, v.w);
    }
    __syncthreads();

    // ---------------- Phase 1: thread = (c4: 64 col-quads, rh: 8 row-slices), all 8 atoms
    const int c4 = tid & 63;
    const int rh = tid >> 6;
    ull acc0[8], acc1[8];
    {
        const int r0 = rh * 64;
        const ulonglong2* rbase = (const ulonglong2*)(reductors + (size_t)s * 131072)
                                  + (size_t)r0 * 64 + c4;
        #pragma unroll
        for (int a = 0; a < 8; ++a) { acc0[a] = 0ull; acc1[a] = 0ull; }
        ulonglong2 bufA = rbase[0];
        ulonglong2 bufB = rbase[64];
        #pragma unroll 1
        for (int rr = 0; rr < 64; rr += 2) {
            ulonglong2 ca = bufA, cb = bufB;
            if (rr + 2 < 64) { bufA = rbase[(rr + 2) * 64]; bufB = rbase[(rr + 3) * 64]; }
            const ulonglong2* rp = (const ulonglong2*)(bufS + r0 + rr);
            #pragma unroll
            for (int a = 0; a < 8; ++a) {
                ulonglong2 p = rp[a * 256];
                ffma2(acc0[a], p.x, ca.x); ffma2(acc1[a], p.x, ca.y);
                ffma2(acc0[a], p.y, cb.x); ffma2(acc1[a], p.y, cb.y);
            }
        }
    }
    __syncthreads();   // all reads of rep done; bufS becomes merge scratch

    // merge 8 rh-slices -> 4 slices: rh>=4 store; rh<4 add in after sync
    float4* scratch = (float4*)bufS;      // [4][8 atoms][64 quads]
    if (rh >= 4) {
        #pragma unroll
        for (int a = 0; a < 8; ++a) {
            float2 v0 = unpack2(acc0[a]), v1 = unpack2(acc1[a]);
            scratch[(rh - 4) * 512 + a * 64 + c4] = make_float4(v0.x, v0.y, v1.x, v1.y);
        }
    }
    __syncthreads();
    if (rh < 4) {
        #pragma unroll
        for (int a = 0; a < 8; ++a) {
            int idx = rh * 512 + a * 64 + c4;
            float4 t = scratch[idx];
            float2 v0 = unpack2(acc0[a]), v1 = unpack2(acc1[a]);
            scratch[idx] = make_float4(t.x + v0.x, t.y + v0.y, t.z + v1.x, t.w + v1.y);
        }
    } else {
        // warps 8..15 build the D sign bitmask meanwhile
        const float* dsrc = Dmat + (size_t)s * 8192;
        #pragma unroll 1
        for (int k = 0; k < 32; ++k) {
            int word = (w - 8) * 32 + k;
            float dv = dsrc[word * 32 + lane];
            unsigned b = __ballot_sync(0xffffffffu, dv < 0.0f);
            if (lane == 0) dbitsS[word] = b;
        }
    }
    __syncthreads();

    // ---------------- Phase 2 entry: warp (ai, jh); sum 4 slices -> dup-packed x
    const int ai = w >> 1;
    const int jh = w & 1;
    const int atom = atomsS[ai];
    ull XA[4], XB[4];
    {
        float4 sa = make_float4(0.f, 0.f, 0.f, 0.f), sb = sa;
        #pragma unroll
        for (int k = 0; k < 4; ++k) {
            float4 ta = scratch[k * 512 + ai * 64 + lane];
            float4 tb = scratch[k * 512 + ai * 64 + 32 + lane];
            sa.x += ta.x; sa.y += ta.y; sa.z += ta.z; sa.w += ta.w;
            sb.x += tb.x; sb.y += tb.y; sb.z += tb.z; sb.w += tb.w;
        }
        XA[0] = pack2(sa.x * 0.0625f, sa.x * 0.0625f);
        XA[1] = pack2(sa.y * 0.0625f, sa.y * 0.0625f);
        XA[2] = pack2(sa.z * 0.0625f, sa.z * 0.0625f);
        XA[3] = pack2(sa.w * 0.0625f, sa.w * 0.0625f);
        XB[0] = pack2(sb.x * 0.0625f, sb.x * 0.0625f);
        XB[1] = pack2(sb.y * 0.0625f, sb.y * 0.0625f);
        XB[2] = pack2(sb.z * 0.0625f, sb.z * 0.0625f);
        XB[3] = pack2(sb.w * 0.0625f, sb.w * 0.0625f);
    }
    __syncthreads();   // slice reads done; overlay packed bias into bufS

    // packed bias: [pi][p] pairs (bias[jb*256+p], bias[(jb+8)*256+p])
    {
        const float4* bsrc = (const float4*)(bias + (size_t)s * 8192);
        #pragma unroll
        for (int it = 0; it < 2; ++it) {
            int g = tid + 512 * it;            // 0..1023 float4-groups
            int pi = g >> 6, p4 = g & 63;
            int jb = (pi < 8) ? pi : pi + 8;
            float4 lo = __ldg(bsrc + jb * 64 + p4);
            float4 hi = __ldg(bsrc + (jb + 8) * 64 + p4);
            ull* dst = bufS + pi * 256 + p4 * 4;
            dst[0] = pack2(lo.x, hi.x); dst[1] = pack2(lo.y, hi.y);
            dst[2] = pack2(lo.z, hi.z); dst[3] = pack2(lo.w, hi.w);
        }
    }
    __syncthreads();

    // ---------------- Phase 2 loop: 8 stack-pairs (jb, jb+8) per warp
    ull partial2 = 0ull;
    if (atom >= 0) {
        const int wsh = 4 * (lane & 7);
        const int widx = lane >> 3;
        const ull SG0 = (lane & 1)  ? pack2(-1.f, -1.f) : pack2(1.f, 1.f);
        const ull SG1 = (lane & 2)  ? pack2(-1.f, -1.f) : pack2(1.f, 1.f);
        const ull SG2 = (lane & 4)  ? pack2(-1.f, -1.f) : pack2(1.f, 1.f);
        const ull SG3 = (lane & 8)  ? pack2(-1.f, -1.f) : pack2(1.f, 1.f);
        const ull SG4 = (lane & 16) ? pack2(-1.f, -1.f) : pack2(1.f, 1.f);

        #pragma unroll 1
        for (int t = 0; t < 8; ++t) {
            const int jb = (jh == 0) ? t : 16 + t;
            const int pi = jh * 8 + t;

            unsigned nA0 = dbitsS[jb * 8 + widx] >> wsh;
            unsigned nA1 = dbitsS[jb * 8 + 4 + widx] >> wsh;
            unsigned nB0 = dbitsS[jb * 8 + 64 + widx] >> wsh;
            unsigned nB1 = dbitsS[jb * 8 + 68 + widx] >> wsh;

            ull P0 = sgn2(XA[0], (nA0 << 31) & 0x80000000u, (nB0 << 31) & 0x80000000u);
            ull P1 = sgn2(XA[1], (nA0 << 30) & 0x80000000u, (nB0 << 30) & 0x80000000u);
            ull P2 = sgn2(XA[2], (nA0 << 29) & 0x80000000u, (nB0 << 29) & 0x80000000u);
            ull P3 = sgn2(XA[3], (nA0 << 28) & 0x80000000u, (nB0 << 28) & 0x80000000u);
            ull P4 = sgn2(XB[0], (nA1 << 31) & 0x80000000u, (nB1 << 31) & 0x80000000u);
            ull P5 = sgn2(XB[1], (nA1 << 30) & 0x80000000u, (nB1 << 30) & 0x80000000u);
            ull P6 = sgn2(XB[2], (nA1 << 29) & 0x80000000u, (nB1 << 29) & 0x80000000u);
            ull P7 = sgn2(XB[3], (nA1 << 28) & 0x80000000u, (nB1 << 28) & 0x80000000u);

            // register butterflies: h=1, 2, 128 (packed over both stacks)
            BFLY2(P0, P1); BFLY2(P2, P3); BFLY2(P4, P5); BFLY2(P6, P7);
            BFLY2(P0, P2); BFLY2(P1, P3); BFLY2(P4, P6); BFLY2(P5, P7);
            BFLY2(P0, P4); BFLY2(P1, P5); BFLY2(P2, P6); BFLY2(P3, P7);

            // cross-lane butterflies: h = 4,8,16,32,64
            #define SSTAGE2(m, SG)                                   \
                P0 = add2(shfl2(P0, m), (lane & m) ? sub2(0, P0) : P0); \
                P1 = add2(shfl2(P1, m), (lane & m) ? sub2(0, P1) : P1); \
                P2 = add2(shfl2(P2, m), (lane & m) ? sub2(0, P2) : P2); \
                P3 = add2(shfl2(P3, m), (lane & m) ? sub2(0, P3) : P3); \
                P4 = add2(shfl2(P4, m), (lane & m) ? sub2(0, P4) : P4); \
                P5 = add2(shfl2(P5, m), (lane & m) ? sub2(0, P5) : P5); \
                P6 = add2(shfl2(P6, m), (lane & m) ? sub2(0, P6) : P6); \
                P7 = add2(shfl2(P7, m), (lane & m) ? sub2(0, P7) : P7);
            // use fma2 form (1 op) instead of the conditional form above
            #undef SSTAGE2
            #define SSTAGE2(m, SG)                      \
                { ull s0 = shfl2(P0, m); ull t0 = P0; P0 = s0; ffma2(P0, t0, SG); } \
                { ull s1 = shfl2(P1, m); ull t1 = P1; P1 = s1; ffma2(P1, t1, SG); } \
                { ull s2 = shfl2(P2, m); ull t2 = P2; P2 = s2; ffma2(P2, t2, SG); } \
                { ull s3 = shfl2(P3, m); ull t3 = P3; P3 = s3; ffma2(P3, t3, SG); } \
                { ull s4 = shfl2(P4, m); ull t4 = P4; P4 = s4; ffma2(P4, t4, SG); } \
                { ull s5 = shfl2(P5, m); ull t5 = P5; P5 = s5; ffma2(P5, t5, SG); } \
                { ull s6 = shfl2(P6, m); ull t6 = P6; P6 = s6; ffma2(P6, t6, SG); } \
                { ull s7 = shfl2(P7, m); ull t7 = P7; P7 = s7; ffma2(P7, t7, SG); }
            SSTAGE2(1, SG0) SSTAGE2(2, SG1) SSTAGE2(4, SG2) SSTAGE2(8, SG3) SSTAGE2(16, SG4)
            #undef SSTAGE2

            // bias add (packed), cos (scalar halves), alpha dot (packed)
            const ulonglong2* bb = (const ulonglong2*)bufS + pi * 128;
            const ulonglong2* aa = (const ulonglong2*)g_apack + pi * 128;
            ulonglong2 Bq, Aq;
            float2 v; float cl, ch;
            #define COSDOT(P, Bv, Av)                                   \
                { ull xp = add2(P, Bv); v = unpack2(xp);                \
                  cl = __cosf(v.x); ch = __cosf(v.y);                   \
                  ffma2(partial2, pack2(cl, ch), Av); }
            Bq = bb[2 * lane];     Aq = aa[2 * lane];
            COSDOT(P0, Bq.x, Aq.x) COSDOT(P1, Bq.y, Aq.y)
            Bq = bb[2 * lane + 1]; Aq = aa[2 * lane + 1];
            COSDOT(P2, Bq.x, Aq.x) COSDOT(P3, Bq.y, Aq.y)
            Bq = bb[64 + 2 * lane];     Aq = aa[64 + 2 * lane];
            COSDOT(P4, Bq.x, Aq.x) COSDOT(P5, Bq.y, Aq.y)
            Bq = bb[64 + 2 * lane + 1]; Aq = aa[64 + 2 * lane + 1];
            COSDOT(P6, Bq.x, Aq.x) COSDOT(P7, Bq.y, Aq.y)
            #undef COSDOT
        }
    }

    float partial;
    {
        float2 v = unpack2(partial2);
        partial = v.x + v.y;
        #pragma unroll
        for (int o = 16; o; o >>= 1) partial += __shfl_xor_sync(0xffffffffu, partial, o);
    }
    if (lane == 0) wpartS[w] = partial;
    __syncthreads();
    if (jh == 0 && lane == 0 && atom >= 0)
        atomicAdd(&out[atom >> 6], (wpartS[w] + wpartS[w + 1]) * 0.015625f);  // FEAT_NORM
}

extern "C" void kernel_launch(void* const* d_in, const int* in_sizes, int n_in,
                              void* d_out, int out_size) {
    (void)in_sizes; (void)n_in; (void)out_size;
    const float* rep       = (const float*)d_in[0];
    const int*   charges   = (const int*)d_in[1];
    const float* reductors = (const float*)d_in[2];
    const float* Dmat      = (const float*)d_in[3];
    const float* bias      = (const float*)d_in[4];
    const float* alpha     = (const float*)d_in[5];
    float* out = (float*)d_out;

    prep_kernel<<<1, 256>>>(charges, alpha, out);
    sorf_kernel<<<MAXCHUNK, 512>>>(rep, reductors, Dmat, bias, out);
}

// round 10
// speedup vs baseline: 1.1315x; 1.1315x over previous
#include <cuda_runtime.h>

// SORF fused: out[m] = (1/64) * sum_a alpha . cos( (1/16) H (D_s ⊙ (rep[m,a] @ red[s])) + bias_s )
// ATOMS=7 per CTA -> ~296 CTAs = exactly 2/SM on GB300 (148 SMs), balanced single wave.
// Phase 1: GEMV f32x2, reductors read once/CTA, rh-partials tree-merged (no atomics);
//          idle warps build the D sign bitmask during the merge.
// Phase 2: warp = (atom, j-half); scalar FWHT(256) registers+shfl; bias smem, alpha L1.

#define ATOMS 7
#define NATOMS 2048
#define MAXCHUNK 300

typedef unsigned long long ull;

__device__ int g_count[4];
__device__ int g_list[4 * NATOMS];
__device__ int g_tabS[MAXCHUNK];
__device__ int g_tabStart[MAXCHUNK];
__device__ int g_nchunks;

__device__ __forceinline__ ull pack2(float a, float b) {
    ull r; asm("mov.b64 %0, {%1, %2};" : "=l"(r) : "f"(a), "f"(b)); return r;
}
__device__ __forceinline__ float2 unpack2(ull v) {
    float2 r; asm("mov.b64 {%0, %1}, %2;" : "=f"(r.x), "=f"(r.y) : "l"(v)); return r;
}
__device__ __forceinline__ void ffma2(ull& acc, ull a, ull b) {
    asm("fma.rn.f32x2 %0, %1, %2, %0;" : "+l"(acc) : "l"(a), "l"(b));
}
#define BFLY(a, b) do { float t_ = (a); (a) = t_ + (b); (b) = t_ - (b); } while (0)

// ---- prep: smem-staged charges, ballot compaction, dense chunk table ----
__global__ void prep_kernel(const int* __restrict__ charges, float* __restrict__ out) {
    __shared__ int chS[NATOMS];
    __shared__ int cntS[4];
    const int tid = threadIdx.x;          // 256 threads
    if (tid < 32) out[tid] = 0.0f;
    #pragma unroll
    for (int i = 0; i < NATOMS / 256; ++i) chS[tid + 256 * i] = charges[tid + 256 * i];
    __syncthreads();
    const int lane = tid & 31;
    const int w = tid >> 5;
    if (w < 4) {
        int cnt = 0;
        const unsigned lt = (1u << lane) - 1u;
        #pragma unroll 1
        for (int base = 0; base < NATOMS; base += 32) {
            int c = chS[base + lane];
            unsigned m = __ballot_sync(0xffffffffu, c == w);
            if (c == w) g_list[w * NATOMS + cnt + __popc(m & lt)] = base + lane;
            cnt += __popc(m);
        }
        if (lane == 0) { g_count[w] = cnt; cntS[w] = cnt; }
    }
    __syncthreads();
    int offs[5];
    offs[0] = 0;
    #pragma unroll
    for (int s = 0; s < 4; ++s) offs[s + 1] = offs[s] + ((cntS[s] + ATOMS - 1) / ATOMS);
    for (int c = tid; c < offs[4]; c += 256) {
        int s = (c >= offs[1]) + (c >= offs[2]) + (c >= offs[3]);
        g_tabS[c] = s;
        g_tabStart[c] = (c - offs[s]) * ATOMS;
    }
    if (tid == 0) g_nchunks = offs[4];
}

__global__ void __launch_bounds__(512, 2) sorf_kernel(
    const float* __restrict__ rep,
    const float* __restrict__ reductors,
    const float* __restrict__ Dmat,
    const float* __restrict__ bias,
    const float* __restrict__ alpha,
    float* __restrict__ out)
{
    const int c = blockIdx.x;
    if (c >= g_nchunks) return;
    const int s = g_tabS[c];
    const int start = g_tabStart[c];
    const int n = g_count[s];
    const int cnt = min(ATOMS, n - start);

    // 32 KB multi-use: rep {v,v} pairs (28KB) -> merge scratch (4 x 7KB) -> bias (32KB)
    __shared__ ull bufS[4096];
    __shared__ unsigned dbitsS[256];          // 32 stacks x 8 words of sign bits
    __shared__ int atomsS[8];
    __shared__ float wpartS[16];

    const int tid = threadIdx.x;
    const int lane = tid & 31;
    const int w = tid >> 5;                   // 16 warps

    if (tid < 8) atomsS[tid] = (tid < cnt) ? g_list[s * NATOMS + start + tid] : -1;
    __syncthreads();

    // rep -> duplicated pairs: repdup[atom][r] = {rep_r, rep_r}; 7 atoms x 128 quads
    #pragma unroll
    for (int it = 0; it < 2; ++it) {
        int idx = tid + 512 * it;
        if (idx < ATOMS * 128) {
            int ai = idx >> 7, q = idx & 127;
            int atom = atomsS[ai];
            float4 v = (atom >= 0) ? ((const float4*)rep)[(size_t)atom * 128 + q]
                                   : make_float4(0.f, 0.f, 0.f, 0.f);
            ull* d = bufS + ai * 512 + q * 4;
            d[0] = pack2(v.x, v.x); d[1] = pack2(v.y, v.y);
            d[2] = pack2(v.z, v.z); d[3] = pack2(v.w, v.w);
        }
    }
    __syncthreads();

    // ---------------- Phase 1: thread = (c4: 64 col-quads, rh: 8 row-slices), all 7 atoms
    const int c4 = tid & 63;
    const int rh = tid >> 6;
    ull acc0[ATOMS], acc1[ATOMS];
    {
        const int r0 = rh * 64;
        const ulonglong2* rbase = (const ulonglong2*)(reductors + (size_t)s * 131072)
                                  + (size_t)r0 * 64 + c4;
        #pragma unroll
        for (int a = 0; a < ATOMS; ++a) { acc0[a] = 0ull; acc1[a] = 0ull; }
        ulonglong2 bufA = rbase[0];
        ulonglong2 bufB = rbase[64];
        #pragma unroll 1
        for (int rr = 0; rr < 64; rr += 2) {
            ulonglong2 ca = bufA, cb = bufB;
            if (rr + 2 < 64) { bufA = rbase[(rr + 2) * 64]; bufB = rbase[(rr + 3) * 64]; }
            const ulonglong2* rp = (const ulonglong2*)(bufS + r0 + rr);
            #pragma unroll
            for (int a = 0; a < ATOMS; ++a) {
                ulonglong2 p = rp[a * 256];    // broadcast LDS.128
                ffma2(acc0[a], p.x, ca.x); ffma2(acc1[a], p.x, ca.y);
                ffma2(acc0[a], p.y, cb.x); ffma2(acc1[a], p.y, cb.y);
            }
        }
    }
    __syncthreads();   // rep reads done; bufS becomes merge scratch [4][7 atoms][64 quads]

    float4* scratch = (float4*)bufS;
    if (rh >= 4) {
        #pragma unroll
        for (int a = 0; a < ATOMS; ++a) {
            float2 v0 = unpack2(acc0[a]), v1 = unpack2(acc1[a]);
            scratch[(rh - 4) * (ATOMS * 64) + a * 64 + c4] = make_float4(v0.x, v0.y, v1.x, v1.y);
        }
    }
    __syncthreads();
    if (rh < 4) {
        #pragma unroll
        for (int a = 0; a < ATOMS; ++a) {
            int idx = rh * (ATOMS * 64) + a * 64 + c4;
            float4 t = scratch[idx];
            float2 v0 = unpack2(acc0[a]), v1 = unpack2(acc1[a]);
            scratch[idx] = make_float4(t.x + v0.x, t.y + v0.y, t.z + v1.x, t.w + v1.y);
        }
    } else {
        // warps 8..15 build the D sign bitmask meanwhile
        const float* dsrc = Dmat + (size_t)s * 8192;
        #pragma unroll 1
        for (int k = 0; k < 32; ++k) {
            int word = (w - 8) * 32 + k;
            float dv = dsrc[word * 32 + lane];
            unsigned b = __ballot_sync(0xffffffffu, dv < 0.0f);
            if (lane == 0) dbitsS[word] = b;
        }
    }
    __syncthreads();

    // ---------------- Phase 2 entry: warp (ai, jh); sum 4 slices -> registers
    const int ai = w >> 1;                    // 0..7 ; ai==7 idle
    const int jh = w & 1;
    const int atom = (ai < ATOMS) ? atomsS[ai] : -1;
    float4 xa4 = make_float4(0.f, 0.f, 0.f, 0.f), xb4 = xa4;
    if (atom >= 0) {
        #pragma unroll
        for (int k = 0; k < 4; ++k) {
            float4 ta = scratch[k * (ATOMS * 64) + ai * 64 + lane];
            float4 tb = scratch[k * (ATOMS * 64) + ai * 64 + 32 + lane];
            xa4.x += ta.x; xa4.y += ta.y; xa4.z += ta.z; xa4.w += ta.w;
            xb4.x += tb.x; xb4.y += tb.y; xb4.z += tb.z; xb4.w += tb.w;
        }
        xa4.x *= 0.0625f; xa4.y *= 0.0625f; xa4.z *= 0.0625f; xa4.w *= 0.0625f;
        xb4.x *= 0.0625f; xb4.y *= 0.0625f; xb4.z *= 0.0625f; xb4.w *= 0.0625f;
    }
    __syncthreads();   // slice reads done; overlay bias into bufS

    {
        float4* dst = (float4*)bufS;
        const float4* src = (const float4*)(bias + (size_t)s * 8192);
        #pragma unroll
        for (int it = 0; it < 4; ++it) dst[tid + 512 * it] = src[tid + 512 * it];
    }
    __syncthreads();

    // ---------------- Phase 2 loop: 16 stacks per warp (j-half jh)
    // x[c] holds p = 4*lane+c ; x[4+c] holds p = 128+4*lane+c
    float pA = 0.f, pB = 0.f;
    if (atom >= 0) {
        const float4* bb4 = (const float4*)bufS;
        const float4* al4 = (const float4*)alpha;
        const int wsh = 4 * (lane & 7);
        const int widx = lane >> 3;
        const float sg0 = (lane & 1) ? -1.f : 1.f;
        const float sg1 = (lane & 2) ? -1.f : 1.f;
        const float sg2 = (lane & 4) ? -1.f : 1.f;
        const float sg3 = (lane & 8) ? -1.f : 1.f;
        const float sg4 = (lane & 16) ? -1.f : 1.f;

        #pragma unroll 1
        for (int j = 16 * jh; j < 16 * jh + 16; ++j) {
            unsigned n0 = dbitsS[j * 8 + widx] >> wsh;
            unsigned n1 = dbitsS[j * 8 + 4 + widx] >> wsh;
            float x0 = __uint_as_float(__float_as_uint(xa4.x) ^ ((n0 << 31) & 0x80000000u));
            float x1 = __uint_as_float(__float_as_uint(xa4.y) ^ ((n0 << 30) & 0x80000000u));
            float x2 = __uint_as_float(__float_as_uint(xa4.z) ^ ((n0 << 29) & 0x80000000u));
            float x3 = __uint_as_float(__float_as_uint(xa4.w) ^ ((n0 << 28) & 0x80000000u));
            float x4 = __uint_as_float(__float_as_uint(xb4.x) ^ ((n1 << 31) & 0x80000000u));
            float x5 = __uint_as_float(__float_as_uint(xb4.y) ^ ((n1 << 30) & 0x80000000u));
            float x6 = __uint_as_float(__float_as_uint(xb4.z) ^ ((n1 << 29) & 0x80000000u));
            float x7 = __uint_as_float(__float_as_uint(xb4.w) ^ ((n1 << 28) & 0x80000000u));

            // register butterflies: h=1, h=2, h=128
            BFLY(x0, x1); BFLY(x2, x3); BFLY(x4, x5); BFLY(x6, x7);
            BFLY(x0, x2); BFLY(x1, x3); BFLY(x4, x6); BFLY(x5, x7);
            BFLY(x0, x4); BFLY(x1, x5); BFLY(x2, x6); BFLY(x3, x7);

            // cross-lane butterflies: h = 4,8,16,32,64
            #define SSTAGE(m, sg)                                                  \
                x0 = fmaf(x0, sg, __shfl_xor_sync(0xffffffffu, x0, m));            \
                x1 = fmaf(x1, sg, __shfl_xor_sync(0xffffffffu, x1, m));            \
                x2 = fmaf(x2, sg, __shfl_xor_sync(0xffffffffu, x2, m));            \
                x3 = fmaf(x3, sg, __shfl_xor_sync(0xffffffffu, x3, m));            \
                x4 = fmaf(x4, sg, __shfl_xor_sync(0xffffffffu, x4, m));            \
                x5 = fmaf(x5, sg, __shfl_xor_sync(0xffffffffu, x5, m));            \
                x6 = fmaf(x6, sg, __shfl_xor_sync(0xffffffffu, x6, m));            \
                x7 = fmaf(x7, sg, __shfl_xor_sync(0xffffffffu, x7, m));
            SSTAGE(1, sg0) SSTAGE(2, sg1) SSTAGE(4, sg2) SSTAGE(8, sg3) SSTAGE(16, sg4)
            #undef SSTAGE

            float4 b0 = bb4[j * 64 + lane];
            float4 b1 = bb4[j * 64 + 32 + lane];
            float4 a0 = __ldg(&al4[j * 64 + lane]);
            float4 a1 = __ldg(&al4[j * 64 + 32 + lane]);
            pA = fmaf(__cosf(x0 + b0.x), a0.x, pA);
            pA = fmaf(__cosf(x1 + b0.y), a0.y, pA);
            pA = fmaf(__cosf(x2 + b0.z), a0.z, pA);
            pA = fmaf(__cosf(x3 + b0.w), a0.w, pA);
            pB = fmaf(__cosf(x4 + b1.x), a1.x, pB);
            pB = fmaf(__cosf(x5 + b1.y), a1.y, pB);
            pB = fmaf(__cosf(x6 + b1.z), a1.z, pB);
            pB = fmaf(__cosf(x7 + b1.w), a1.w, pB);
        }
    }

    float partial = pA + pB;
    #pragma unroll
    for (int o = 16; o; o >>= 1) partial += __shfl_xor_sync(0xffffffffu, partial, o);
    if (lane == 0) wpartS[w] = partial;
    __syncthreads();
    if (jh == 0 && lane == 0 && atom >= 0)
        atomicAdd(&out[atom >> 6], (wpartS[w] + wpartS[w + 1]) * 0.015625f);  // FEAT_NORM
}

extern "C" void kernel_launch(void* const* d_in, const int* in_sizes, int n_in,
                              void* d_out, int out_size) {
    (void)in_sizes; (void)n_in; (void)out_size;
    const float* rep       = (const float*)d_in[0];
    const int*   charges   = (const int*)d_in[1];
    const float* reductors = (const float*)d_in[2];
    const float* Dmat      = (const float*)d_in[3];
    const float* bias      = (const float*)d_in[4];
    const float* alpha     = (const float*)d_in[5];
    float* out = (float*)d_out;

    prep_kernel<<<1, 256>>>(charges, out);
    sorf_kernel<<<MAXCHUNK, 512>>>(rep, reductors, Dmat, bias, alpha, out);
}